// round 2
// baseline (speedup 1.0000x reference)
#include <cuda_runtime.h>
#include <cstdint>

#define BTOT    65536
#define TSTEPS  15
#define HID     128
#define INDIM   6
#define OUTDIM  3
#define HORZ    10
#define G4      512     // 4*HID
#define MROWS   64      // batch rows per CTA
#define NTHR    256
#define XROW    90      // TSTEPS*INDIM

// ---------------- persistent scratch (allowed: __device__ globals) ----------------
__device__ __align__(16) float g_T_ih0[INDIM * G4];   // [k][j] transposed
__device__ __align__(16) float g_T_hh0[HID * G4];
__device__ __align__(16) float g_T_ih1[HID * G4];
__device__ __align__(16) float g_T_hh1[HID * G4];
__device__ __align__(16) float g_T_ihd[HID * G4];
__device__ __align__(16) float g_T_hhd[HID * G4];
__device__ __align__(16) float g_based[HORZ * HID];   // bp + emb[s] @ Wp[:,3:]^T
__device__ __align__(16) float g_WpT3[3 * HID];       // Wp[:, :3] transposed

// ---------------- prep kernels ----------------
__global__ void prep_transpose(const float* __restrict__ ih0,
                               const float* __restrict__ hh0,
                               const float* __restrict__ ih1,
                               const float* __restrict__ hh1,
                               const float* __restrict__ ihd,
                               const float* __restrict__ hhd) {
    int idx = blockIdx.x * blockDim.x + threadIdx.x;
    if (idx < 5 * 65536) {
        int m = idx >> 16;
        int e = idx & 65535;
        int k = e >> 9, j = e & 511;       // e = k*512 + j
        const float* s = (m == 0) ? hh0 : (m == 1) ? ih1 : (m == 2) ? hh1 : (m == 3) ? ihd : hhd;
        float v = s[j * HID + k];
        float* d = (m == 0) ? g_T_hh0 : (m == 1) ? g_T_ih1 : (m == 2) ? g_T_hh1 : (m == 3) ? g_T_ihd : g_T_hhd;
        d[e] = v;
    } else {
        int e = idx - 5 * 65536;
        if (e < INDIM * G4) {
            int k = e >> 9, j = e & 511;
            g_T_ih0[e] = ih0[j * INDIM + k];
        }
    }
}

__global__ void prep_small(const float* __restrict__ emb,
                           const float* __restrict__ Wp,
                           const float* __restrict__ bp) {
    int idx = blockIdx.x * blockDim.x + threadIdx.x;
    if (idx < HORZ * HID) {
        int s = idx / HID, j = idx - s * HID;
        float acc = bp[j];
        const float* e = emb + s * HID;
        const float* w = Wp + j * (OUTDIM + HID) + OUTDIM;
        #pragma unroll 8
        for (int k = 0; k < HID; k++) acc += e[k] * w[k];
        g_based[idx] = acc;
    }
    if (idx < 3 * HID) {
        int k = idx / HID, j = idx - k * HID;
        g_WpT3[idx] = Wp[j * (OUTDIM + HID) + k];
    }
}

// ---------------- device helpers ----------------
__device__ __forceinline__ float sigf(float x) {
    x = fminf(fmaxf(x, -30.f), 30.f);
    return __fdividef(1.f, 1.f + __expf(-x));
}
__device__ __forceinline__ float tanhf_f(float x) {
    x = fminf(fmaxf(x, -15.f), 15.f);
    float e = __expf(-2.f * x);
    return __fdividef(1.f - e, 1.f + e);
}
__device__ __forceinline__ float wred(float v) {
    v += __shfl_xor_sync(0xffffffffu, v, 16);
    v += __shfl_xor_sync(0xffffffffu, v, 8);
    v += __shfl_xor_sync(0xffffffffu, v, 4);
    v += __shfl_xor_sync(0xffffffffu, v, 2);
    v += __shfl_xor_sync(0xffffffffu, v, 1);
    return v;
}

__device__ __forceinline__ void fma16(float (&acc)[8][4][4], int r, float av,
                                      const float4& w0, const float4& w1,
                                      const float4& w2, const float4& w3) {
    acc[r][0][0] += av * w0.x; acc[r][0][1] += av * w0.y; acc[r][0][2] += av * w0.z; acc[r][0][3] += av * w0.w;
    acc[r][1][0] += av * w1.x; acc[r][1][1] += av * w1.y; acc[r][1][2] += av * w1.z; acc[r][1][3] += av * w1.w;
    acc[r][2][0] += av * w2.x; acc[r][2][1] += av * w2.y; acc[r][2][2] += av * w2.z; acc[r][2][3] += av * w2.w;
    acc[r][3][0] += av * w3.x; acc[r][3][1] += av * w3.y; acc[r][3][2] += av * w3.z; acc[r][3][3] += av * w3.w;
}

// 64x512 += A[64x128] * Wt[128x512]; Wt streamed gmem->smem double-buffered.
__device__ __forceinline__ void gemm_k128(float (&acc)[8][4][4],
                                          const float* __restrict__ Wt,
                                          const float* __restrict__ As,
                                          float* __restrict__ wbuf,
                                          int tid, int r0, int cg4) {
    const float4* src = (const float4*)Wt;
    float4* wb4 = (float4*)wbuf;
    float4 pre[4];
    #pragma unroll
    for (int i = 0; i < 4; i++) pre[i] = src[tid + 256 * i];
    #pragma unroll
    for (int i = 0; i < 4; i++) wb4[tid + 256 * i] = pre[i];
    __syncthreads();
    int cur = 0;
    #pragma unroll 1
    for (int t = 0; t < 16; ++t) {
        if (t < 15) {
            #pragma unroll
            for (int i = 0; i < 4; i++) pre[i] = src[(t + 1) * 1024 + tid + 256 * i];
        }
        const float* wt = wbuf + cur * 4096;
        #pragma unroll
        for (int kk = 0; kk < 8; kk += 4) {
            float4 a4[8];
            #pragma unroll
            for (int r = 0; r < 8; r++)
                a4[r] = *(const float4*)&As[(r0 + r) * HID + t * 8 + kk];
            #pragma unroll
            for (int i = 0; i < 4; i++) {
                const float* wrow = wt + (kk + i) * G4 + cg4;
                float4 w0 = *(const float4*)(wrow);
                float4 w1 = *(const float4*)(wrow + 128);
                float4 w2 = *(const float4*)(wrow + 256);
                float4 w3 = *(const float4*)(wrow + 384);
                #pragma unroll
                for (int r = 0; r < 8; r++) {
                    float av = (i == 0) ? a4[r].x : ((i == 1) ? a4[r].y : ((i == 2) ? a4[r].z : a4[r].w));
                    fma16(acc, r, av, w0, w1, w2, w3);
                }
            }
        }
        if (t < 15) {
            int nxt = cur ^ 1;
            #pragma unroll
            for (int i = 0; i < 4; i++) wb4[nxt * 1024 + tid + 256 * i] = pre[i];
            cur = nxt;
        }
        __syncthreads();
    }
}

__device__ __forceinline__ void cell_update(float (&acc)[8][4][4],
                                            const float* __restrict__ bias,
                                            float* hS, float* cS, int r0, int cg4) {
    float4 bi4 = *(const float4*)(bias + cg4);
    float4 bf4 = *(const float4*)(bias + cg4 + 128);
    float4 bg4 = *(const float4*)(bias + cg4 + 256);
    float4 bo4 = *(const float4*)(bias + cg4 + 384);
    float bi[4] = {bi4.x, bi4.y, bi4.z, bi4.w};
    float bf[4] = {bf4.x, bf4.y, bf4.z, bf4.w};
    float bg[4] = {bg4.x, bg4.y, bg4.z, bg4.w};
    float bo[4] = {bo4.x, bo4.y, bo4.z, bo4.w};
    #pragma unroll
    for (int r = 0; r < 8; r++) {
        int row = r0 + r;
        float4 c4 = *(const float4*)(cS + row * HID + cg4);
        float cc[4] = {c4.x, c4.y, c4.z, c4.w};
        float hh[4];
        #pragma unroll
        for (int q = 0; q < 4; q++) {
            float ig = sigf(acc[r][0][q] + bi[q]);
            float fg = sigf(acc[r][1][q] + bf[q]);
            float gv = tanhf_f(acc[r][2][q] + bg[q]);
            float og = sigf(acc[r][3][q] + bo[q]);
            float cn = fg * cc[q] + ig * gv;
            cc[q] = cn;
            hh[q] = og * tanhf_f(cn);
        }
        *(float4*)(cS + row * HID + cg4) = make_float4(cc[0], cc[1], cc[2], cc[3]);
        *(float4*)(hS + row * HID + cg4) = make_float4(hh[0], hh[1], hh[2], hh[3]);
    }
}

// ---------------- main fused persistent kernel ----------------
// smem floats:
// sT_ih0 3072 | sX 5760 | h0s 8192 | h1s 8192 | c0s 8192 | c1s 8192 | wbuf 8192 | prevb 256
#define SMEM_FLOATS (3072 + 5760 + 8192 * 4 + 8192 + 256)
#define SMEM_BYTES  (SMEM_FLOATS * 4)

extern __shared__ float smem[];

__global__ void __launch_bounds__(NTHR, 1)
traj_kernel(const float* __restrict__ x,
            const float* __restrict__ b0, const float* __restrict__ b1,
            const float* __restrict__ bd,
            const float* __restrict__ Wm, const float* __restrict__ bm,
            const float* __restrict__ Ws, const float* __restrict__ bs,
            const float* __restrict__ ln_g, const float* __restrict__ ln_b,
            float* __restrict__ out) {
    float* sT_ih0 = smem;
    float* sX   = sT_ih0 + 3072;
    float* h0s  = sX + 5760;
    float* h1s  = h0s + 8192;
    float* c0s  = h1s + 8192;
    float* c1s  = c0s + 8192;
    float* wbuf = c1s + 8192;
    float* prevb = wbuf + 8192;

    const int tid = threadIdx.x;
    const int cg = tid & 31, rg = tid >> 5;
    const int cg4 = cg * 4, r0 = rg * 8;
    const int base = blockIdx.x * MROWS;

    for (int i = tid; i < INDIM * G4; i += NTHR) sT_ih0[i] = g_T_ih0[i];
    {
        const float4* xsrc = (const float4*)(x + (size_t)base * XROW);
        float4* xdst = (float4*)sX;
        for (int i = tid; i < (MROWS * XROW) / 4; i += NTHR) xdst[i] = xsrc[i];
    }
    for (int i = tid; i < MROWS * HID; i += NTHR) {
        h0s[i] = 0.f; h1s[i] = 0.f; c0s[i] = 0.f; c1s[i] = 0.f;
    }
    __syncthreads();

    float acc[8][4][4];

    // ---------------- encoder: 15 steps, layer0 + layer1 fused per step ----------------
    for (int t = 0; t < TSTEPS; t++) {
        // layer 0: g = x_t @ Wih0^T + h0 @ Whh0^T
        #pragma unroll
        for (int r = 0; r < 8; r++)
            #pragma unroll
            for (int g = 0; g < 4; g++)
                #pragma unroll
                for (int q = 0; q < 4; q++) acc[r][g][q] = 0.f;
        #pragma unroll
        for (int k = 0; k < INDIM; k++) {
            const float* wrow = sT_ih0 + k * G4 + cg4;
            float4 w0 = *(const float4*)(wrow);
            float4 w1 = *(const float4*)(wrow + 128);
            float4 w2 = *(const float4*)(wrow + 256);
            float4 w3 = *(const float4*)(wrow + 384);
            #pragma unroll
            for (int r = 0; r < 8; r++) {
                float av = sX[(r0 + r) * XROW + t * INDIM + k];
                fma16(acc, r, av, w0, w1, w2, w3);
            }
        }
        gemm_k128(acc, g_T_hh0, h0s, wbuf, tid, r0, cg4);
        cell_update(acc, b0, h0s, c0s, r0, cg4);

        // layer 1: g = h0_new @ Wih1^T + h1 @ Whh1^T
        #pragma unroll
        for (int r = 0; r < 8; r++)
            #pragma unroll
            for (int g = 0; g < 4; g++)
                #pragma unroll
                for (int q = 0; q < 4; q++) acc[r][g][q] = 0.f;
        gemm_k128(acc, g_T_ih1, h0s, wbuf, tid, r0, cg4);
        gemm_k128(acc, g_T_hh1, h1s, wbuf, tid, r0, cg4);
        cell_update(acc, b1, h1s, c1s, r0, cg4);
    }
    __syncthreads();

    // prev0 = x[:, -1, :3]
    if (tid < MROWS) {
        prevb[tid * 4 + 0] = sX[tid * XROW + 84];
        prevb[tid * 4 + 1] = sX[tid * XROW + 85];
        prevb[tid * 4 + 2] = sX[tid * XROW + 86];
    }
    __syncthreads();

    // ---------------- decoder: 10 steps ----------------
    const size_t LOGOFF = (size_t)BTOT * HORZ * OUTDIM;
    for (int s = 0; s < HORZ; s++) {
        // dec_in = relu(base_d[s] + prev @ WpT3) -> h0s
        {
            float4 ba = *(const float4*)&g_based[s * HID + cg4];
            float4 wp0 = *(const float4*)&g_WpT3[0 * HID + cg4];
            float4 wp1 = *(const float4*)&g_WpT3[1 * HID + cg4];
            float4 wp2 = *(const float4*)&g_WpT3[2 * HID + cg4];
            #pragma unroll
            for (int r = 0; r < 8; r++) {
                int row = r0 + r;
                float p0 = prevb[row * 4 + 0];
                float p1 = prevb[row * 4 + 1];
                float p2 = prevb[row * 4 + 2];
                float4 d;
                d.x = fmaxf(ba.x + p0 * wp0.x + p1 * wp1.x + p2 * wp2.x, 0.f);
                d.y = fmaxf(ba.y + p0 * wp0.y + p1 * wp1.y + p2 * wp2.y, 0.f);
                d.z = fmaxf(ba.z + p0 * wp0.z + p1 * wp1.z + p2 * wp2.z, 0.f);
                d.w = fmaxf(ba.w + p0 * wp0.w + p1 * wp1.w + p2 * wp2.w, 0.f);
                *(float4*)(h0s + row * HID + cg4) = d;
            }
        }
        #pragma unroll
        for (int r = 0; r < 8; r++)
            #pragma unroll
            for (int g = 0; g < 4; g++)
                #pragma unroll
                for (int q = 0; q < 4; q++) acc[r][g][q] = 0.f;
        gemm_k128(acc, g_T_ihd, h0s, wbuf, tid, r0, cg4);
        gemm_k128(acc, g_T_hhd, h1s, wbuf, tid, r0, cg4);
        cell_update(acc, bd, h1s, c1s, r0, cg4);
        __syncthreads();

        // layernorm + heads; warp rg handles rows r0..r0+7
        {
            int lane = cg;
            float4 g4v = *(const float4*)&ln_g[lane * 4];
            float4 b4v = *(const float4*)&ln_b[lane * 4];
            float4 wm0 = *(const float4*)&Wm[0 * HID + lane * 4];
            float4 wm1 = *(const float4*)&Wm[1 * HID + lane * 4];
            float4 wm2 = *(const float4*)&Wm[2 * HID + lane * 4];
            float4 ws0 = *(const float4*)&Ws[0 * HID + lane * 4];
            float4 ws1 = *(const float4*)&Ws[1 * HID + lane * 4];
            float4 ws2 = *(const float4*)&Ws[2 * HID + lane * 4];
            float bm0 = bm[0], bm1 = bm[1], bm2 = bm[2];
            float bs0 = bs[0], bs1 = bs[1], bs2 = bs[2];
            #pragma unroll 1
            for (int r = 0; r < 8; r++) {
                int row = r0 + r;
                float4 v = *(const float4*)&h1s[row * HID + lane * 4];
                float sum = wred(v.x + v.y + v.z + v.w);
                float mu = sum * (1.f / 128.f);
                float4 dv = make_float4(v.x - mu, v.y - mu, v.z - mu, v.w - mu);
                float ss = wred(dv.x * dv.x + dv.y * dv.y + dv.z * dv.z + dv.w * dv.w);
                float rs = rsqrtf(ss * (1.f / 128.f) + 1e-5f);
                float4 f;
                f.x = dv.x * rs * g4v.x + b4v.x;
                f.y = dv.y * rs * g4v.y + b4v.y;
                f.z = dv.z * rs * g4v.z + b4v.z;
                f.w = dv.w * rs * g4v.w + b4v.w;
                float m0 = wred(f.x * wm0.x + f.y * wm0.y + f.z * wm0.z + f.w * wm0.w);
                float m1 = wred(f.x * wm1.x + f.y * wm1.y + f.z * wm1.z + f.w * wm1.w);
                float m2 = wred(f.x * wm2.x + f.y * wm2.y + f.z * wm2.z + f.w * wm2.w);
                float s0 = wred(f.x * ws0.x + f.y * ws0.y + f.z * ws0.z + f.w * ws0.w);
                float s1 = wred(f.x * ws1.x + f.y * ws1.y + f.z * ws1.z + f.w * ws1.w);
                float s2 = wred(f.x * ws2.x + f.y * ws2.y + f.z * ws2.z + f.w * ws2.w);
                if (lane == 0) {
                    m0 += bm0; m1 += bm1; m2 += bm2;
                    float l0 = fminf(fmaxf(s0 + bs0, -6.f), 3.f);
                    float l1 = fminf(fmaxf(s1 + bs1, -6.f), 3.f);
                    float l2 = fminf(fmaxf(s2 + bs2, -6.f), 3.f);
                    size_t orow = (size_t)(base + row) * (HORZ * OUTDIM) + s * OUTDIM;
                    out[orow + 0] = m0; out[orow + 1] = m1; out[orow + 2] = m2;
                    out[LOGOFF + orow + 0] = l0;
                    out[LOGOFF + orow + 1] = l1;
                    out[LOGOFF + orow + 2] = l2;
                    prevb[row * 4 + 0] = m0;
                    prevb[row * 4 + 1] = m1;
                    prevb[row * 4 + 2] = m2;
                }
            }
        }
        __syncthreads();
    }
}

// ---------------- launch ----------------
extern "C" void kernel_launch(void* const* d_in, const int* in_sizes, int n_in,
                              void* d_out, int out_size) {
    const float* x     = (const float*)d_in[0];
    const float* W_ih0 = (const float*)d_in[1];
    const float* W_hh0 = (const float*)d_in[2];
    const float* b0    = (const float*)d_in[3];
    const float* W_ih1 = (const float*)d_in[4];
    const float* W_hh1 = (const float*)d_in[5];
    const float* b1    = (const float*)d_in[6];
    const float* W_ihd = (const float*)d_in[7];
    const float* W_hhd = (const float*)d_in[8];
    const float* bd    = (const float*)d_in[9];
    const float* emb   = (const float*)d_in[10];
    const float* Wp    = (const float*)d_in[11];
    const float* bp    = (const float*)d_in[12];
    const float* Wm    = (const float*)d_in[13];
    const float* bm    = (const float*)d_in[14];
    const float* Ws    = (const float*)d_in[15];
    const float* bs    = (const float*)d_in[16];
    const float* ln_g  = (const float*)d_in[17];
    const float* ln_b  = (const float*)d_in[18];
    float* out = (float*)d_out;

    (void)in_sizes; (void)n_in; (void)out_size;

    prep_transpose<<<(5 * 65536 + INDIM * G4 + 255) / 256, 256>>>(W_ih0, W_hh0, W_ih1, W_hh1, W_ihd, W_hhd);
    prep_small<<<(HORZ * HID + 255) / 256, 256>>>(emb, Wp, bp);

    cudaFuncSetAttribute(traj_kernel, cudaFuncAttributeMaxDynamicSharedMemorySize, SMEM_BYTES);
    traj_kernel<<<BTOT / MROWS, NTHR, SMEM_BYTES>>>(x, b0, b1, bd, Wm, bm, Ws, bs, ln_g, ln_b, out);
}

// round 3
// speedup vs baseline: 1.0006x; 1.0006x over previous
#include <cuda_runtime.h>
#include <cstdint>

#define BTOT    65536
#define TSTEPS  15
#define HID     128
#define INDIM   6
#define OUTDIM  3
#define HORZ    10
#define G4      512     // 4*HID
#define MROWS   64      // batch rows per CTA
#define NTHR    256
#define XROW    90      // TSTEPS*INDIM

// ---------------- persistent scratch (allowed: __device__ globals) ----------------
__device__ __align__(16) float g_T_ih0[INDIM * G4];   // [k][j] transposed
__device__ __align__(16) float g_T_hh0[HID * G4];
__device__ __align__(16) float g_T_ih1[HID * G4];
__device__ __align__(16) float g_T_hh1[HID * G4];
__device__ __align__(16) float g_T_ihd[HID * G4];
__device__ __align__(16) float g_T_hhd[HID * G4];
__device__ __align__(16) float g_based[HORZ * HID];   // bp + emb[s] @ Wp[:,3:]^T
__device__ __align__(16) float g_WpT3[3 * HID];       // Wp[:, :3] transposed

// ---------------- prep kernels ----------------
__global__ void prep_transpose(const float* __restrict__ ih0,
                               const float* __restrict__ hh0,
                               const float* __restrict__ ih1,
                               const float* __restrict__ hh1,
                               const float* __restrict__ ihd,
                               const float* __restrict__ hhd) {
    int idx = blockIdx.x * blockDim.x + threadIdx.x;
    if (idx < 5 * 65536) {
        int m = idx >> 16;
        int e = idx & 65535;
        int k = e >> 9, j = e & 511;       // e = k*512 + j
        const float* s = (m == 0) ? hh0 : (m == 1) ? ih1 : (m == 2) ? hh1 : (m == 3) ? ihd : hhd;
        float v = s[j * HID + k];
        float* d = (m == 0) ? g_T_hh0 : (m == 1) ? g_T_ih1 : (m == 2) ? g_T_hh1 : (m == 3) ? g_T_ihd : g_T_hhd;
        d[e] = v;
    } else {
        int e = idx - 5 * 65536;
        if (e < INDIM * G4) {
            int k = e >> 9, j = e & 511;
            g_T_ih0[e] = ih0[j * INDIM + k];
        }
    }
}

__global__ void prep_small(const float* __restrict__ emb,
                           const float* __restrict__ Wp,
                           const float* __restrict__ bp) {
    int idx = blockIdx.x * blockDim.x + threadIdx.x;
    if (idx < HORZ * HID) {
        int s = idx / HID, j = idx - s * HID;
        float acc = bp[j];
        const float* e = emb + s * HID;
        const float* w = Wp + j * (OUTDIM + HID) + OUTDIM;
        #pragma unroll 8
        for (int k = 0; k < HID; k++) acc += e[k] * w[k];
        g_based[idx] = acc;
    }
    if (idx < 3 * HID) {
        int k = idx / HID, j = idx - k * HID;
        g_WpT3[idx] = Wp[j * (OUTDIM + HID) + k];
    }
}

// ---------------- device helpers ----------------
__device__ __forceinline__ float sigf(float x) {
    x = fminf(fmaxf(x, -30.f), 30.f);
    return __fdividef(1.f, 1.f + __expf(-x));
}
__device__ __forceinline__ float tanhf_f(float x) {
    x = fminf(fmaxf(x, -15.f), 15.f);
    float e = __expf(-2.f * x);
    return __fdividef(1.f - e, 1.f + e);
}
__device__ __forceinline__ float wred(float v) {
    v += __shfl_xor_sync(0xffffffffu, v, 16);
    v += __shfl_xor_sync(0xffffffffu, v, 8);
    v += __shfl_xor_sync(0xffffffffu, v, 4);
    v += __shfl_xor_sync(0xffffffffu, v, 2);
    v += __shfl_xor_sync(0xffffffffu, v, 1);
    return v;
}

__device__ __forceinline__ void fma16(float (&acc)[8][4][4], int r, float av,
                                      const float4& w0, const float4& w1,
                                      const float4& w2, const float4& w3) {
    acc[r][0][0] += av * w0.x; acc[r][0][1] += av * w0.y; acc[r][0][2] += av * w0.z; acc[r][0][3] += av * w0.w;
    acc[r][1][0] += av * w1.x; acc[r][1][1] += av * w1.y; acc[r][1][2] += av * w1.z; acc[r][1][3] += av * w1.w;
    acc[r][2][0] += av * w2.x; acc[r][2][1] += av * w2.y; acc[r][2][2] += av * w2.z; acc[r][2][3] += av * w2.w;
    acc[r][3][0] += av * w3.x; acc[r][3][1] += av * w3.y; acc[r][3][2] += av * w3.z; acc[r][3][3] += av * w3.w;
}

// 64x512 += A[64x128] * Wt[128x512]; Wt streamed gmem->smem double-buffered.
__device__ __forceinline__ void gemm_k128(float (&acc)[8][4][4],
                                          const float* __restrict__ Wt,
                                          const float* __restrict__ As,
                                          float* __restrict__ wbuf,
                                          int tid, int r0, int cg4) {
    const float4* src = (const float4*)Wt;
    float4* wb4 = (float4*)wbuf;
    float4 pre[4];
    #pragma unroll
    for (int i = 0; i < 4; i++) pre[i] = src[tid + 256 * i];
    #pragma unroll
    for (int i = 0; i < 4; i++) wb4[tid + 256 * i] = pre[i];
    __syncthreads();
    int cur = 0;
    #pragma unroll 1
    for (int t = 0; t < 16; ++t) {
        if (t < 15) {
            #pragma unroll
            for (int i = 0; i < 4; i++) pre[i] = src[(t + 1) * 1024 + tid + 256 * i];
        }
        const float* wt = wbuf + cur * 4096;
        #pragma unroll
        for (int kk = 0; kk < 8; kk += 4) {
            float4 a4[8];
            #pragma unroll
            for (int r = 0; r < 8; r++)
                a4[r] = *(const float4*)&As[(r0 + r) * HID + t * 8 + kk];
            #pragma unroll
            for (int i = 0; i < 4; i++) {
                const float* wrow = wt + (kk + i) * G4 + cg4;
                float4 w0 = *(const float4*)(wrow);
                float4 w1 = *(const float4*)(wrow + 128);
                float4 w2 = *(const float4*)(wrow + 256);
                float4 w3 = *(const float4*)(wrow + 384);
                #pragma unroll
                for (int r = 0; r < 8; r++) {
                    float av = (i == 0) ? a4[r].x : ((i == 1) ? a4[r].y : ((i == 2) ? a4[r].z : a4[r].w));
                    fma16(acc, r, av, w0, w1, w2, w3);
                }
            }
        }
        if (t < 15) {
            int nxt = cur ^ 1;
            #pragma unroll
            for (int i = 0; i < 4; i++) wb4[nxt * 1024 + tid + 256 * i] = pre[i];
            cur = nxt;
        }
        __syncthreads();
    }
}

__device__ __forceinline__ void cell_update(float (&acc)[8][4][4],
                                            const float* __restrict__ bias,
                                            float* hS, float* cS, int r0, int cg4) {
    float4 bi4 = *(const float4*)(bias + cg4);
    float4 bf4 = *(const float4*)(bias + cg4 + 128);
    float4 bg4 = *(const float4*)(bias + cg4 + 256);
    float4 bo4 = *(const float4*)(bias + cg4 + 384);
    float bi[4] = {bi4.x, bi4.y, bi4.z, bi4.w};
    float bf[4] = {bf4.x, bf4.y, bf4.z, bf4.w};
    float bg[4] = {bg4.x, bg4.y, bg4.z, bg4.w};
    float bo[4] = {bo4.x, bo4.y, bo4.z, bo4.w};
    #pragma unroll
    for (int r = 0; r < 8; r++) {
        int row = r0 + r;
        float4 c4 = *(const float4*)(cS + row * HID + cg4);
        float cc[4] = {c4.x, c4.y, c4.z, c4.w};
        float hh[4];
        #pragma unroll
        for (int q = 0; q < 4; q++) {
            float ig = sigf(acc[r][0][q] + bi[q]);
            float fg = sigf(acc[r][1][q] + bf[q]);
            float gv = tanhf_f(acc[r][2][q] + bg[q]);
            float og = sigf(acc[r][3][q] + bo[q]);
            float cn = fg * cc[q] + ig * gv;
            cc[q] = cn;
            hh[q] = og * tanhf_f(cn);
        }
        *(float4*)(cS + row * HID + cg4) = make_float4(cc[0], cc[1], cc[2], cc[3]);
        *(float4*)(hS + row * HID + cg4) = make_float4(hh[0], hh[1], hh[2], hh[3]);
    }
}

// ---------------- main fused persistent kernel ----------------
// smem floats:
// sT_ih0 3072 | sX 5760 | h0s 8192 | h1s 8192 | c0s 8192 | c1s 8192 | wbuf 8192 | prevb 256
#define SMEM_FLOATS (3072 + 5760 + 8192 * 4 + 8192 + 256)
#define SMEM_BYTES  (SMEM_FLOATS * 4)

extern __shared__ float smem[];

__global__ void __launch_bounds__(NTHR, 1)
traj_kernel(const float* __restrict__ x,
            const float* __restrict__ b0, const float* __restrict__ b1,
            const float* __restrict__ bd,
            const float* __restrict__ Wm, const float* __restrict__ bm,
            const float* __restrict__ Ws, const float* __restrict__ bs,
            const float* __restrict__ ln_g, const float* __restrict__ ln_b,
            float* __restrict__ out) {
    float* sT_ih0 = smem;
    float* sX   = sT_ih0 + 3072;
    float* h0s  = sX + 5760;
    float* h1s  = h0s + 8192;
    float* c0s  = h1s + 8192;
    float* c1s  = c0s + 8192;
    float* wbuf = c1s + 8192;
    float* prevb = wbuf + 8192;

    const int tid = threadIdx.x;
    const int cg = tid & 31, rg = tid >> 5;
    const int cg4 = cg * 4, r0 = rg * 8;
    const int base = blockIdx.x * MROWS;

    for (int i = tid; i < INDIM * G4; i += NTHR) sT_ih0[i] = g_T_ih0[i];
    {
        const float4* xsrc = (const float4*)(x + (size_t)base * XROW);
        float4* xdst = (float4*)sX;
        for (int i = tid; i < (MROWS * XROW) / 4; i += NTHR) xdst[i] = xsrc[i];
    }
    for (int i = tid; i < MROWS * HID; i += NTHR) {
        h0s[i] = 0.f; h1s[i] = 0.f; c0s[i] = 0.f; c1s[i] = 0.f;
    }
    __syncthreads();

    float acc[8][4][4];

    // ---------------- encoder: 15 steps, layer0 + layer1 fused per step ----------------
    for (int t = 0; t < TSTEPS; t++) {
        // layer 0: g = x_t @ Wih0^T + h0 @ Whh0^T
        #pragma unroll
        for (int r = 0; r < 8; r++)
            #pragma unroll
            for (int g = 0; g < 4; g++)
                #pragma unroll
                for (int q = 0; q < 4; q++) acc[r][g][q] = 0.f;
        #pragma unroll
        for (int k = 0; k < INDIM; k++) {
            const float* wrow = sT_ih0 + k * G4 + cg4;
            float4 w0 = *(const float4*)(wrow);
            float4 w1 = *(const float4*)(wrow + 128);
            float4 w2 = *(const float4*)(wrow + 256);
            float4 w3 = *(const float4*)(wrow + 384);
            #pragma unroll
            for (int r = 0; r < 8; r++) {
                float av = sX[(r0 + r) * XROW + t * INDIM + k];
                fma16(acc, r, av, w0, w1, w2, w3);
            }
        }
        gemm_k128(acc, g_T_hh0, h0s, wbuf, tid, r0, cg4);
        cell_update(acc, b0, h0s, c0s, r0, cg4);

        // layer 1: g = h0_new @ Wih1^T + h1 @ Whh1^T
        #pragma unroll
        for (int r = 0; r < 8; r++)
            #pragma unroll
            for (int g = 0; g < 4; g++)
                #pragma unroll
                for (int q = 0; q < 4; q++) acc[r][g][q] = 0.f;
        gemm_k128(acc, g_T_ih1, h0s, wbuf, tid, r0, cg4);
        gemm_k128(acc, g_T_hh1, h1s, wbuf, tid, r0, cg4);
        cell_update(acc, b1, h1s, c1s, r0, cg4);
    }
    __syncthreads();

    // prev0 = x[:, -1, :3]
    if (tid < MROWS) {
        prevb[tid * 4 + 0] = sX[tid * XROW + 84];
        prevb[tid * 4 + 1] = sX[tid * XROW + 85];
        prevb[tid * 4 + 2] = sX[tid * XROW + 86];
    }
    __syncthreads();

    // ---------------- decoder: 10 steps ----------------
    const size_t LOGOFF = (size_t)BTOT * HORZ * OUTDIM;
    for (int s = 0; s < HORZ; s++) {
        // dec_in = relu(base_d[s] + prev @ WpT3) -> h0s
        {
            float4 ba = *(const float4*)&g_based[s * HID + cg4];
            float4 wp0 = *(const float4*)&g_WpT3[0 * HID + cg4];
            float4 wp1 = *(const float4*)&g_WpT3[1 * HID + cg4];
            float4 wp2 = *(const float4*)&g_WpT3[2 * HID + cg4];
            #pragma unroll
            for (int r = 0; r < 8; r++) {
                int row = r0 + r;
                float p0 = prevb[row * 4 + 0];
                float p1 = prevb[row * 4 + 1];
                float p2 = prevb[row * 4 + 2];
                float4 d;
                d.x = fmaxf(ba.x + p0 * wp0.x + p1 * wp1.x + p2 * wp2.x, 0.f);
                d.y = fmaxf(ba.y + p0 * wp0.y + p1 * wp1.y + p2 * wp2.y, 0.f);
                d.z = fmaxf(ba.z + p0 * wp0.z + p1 * wp1.z + p2 * wp2.z, 0.f);
                d.w = fmaxf(ba.w + p0 * wp0.w + p1 * wp1.w + p2 * wp2.w, 0.f);
                *(float4*)(h0s + row * HID + cg4) = d;
            }
        }
        #pragma unroll
        for (int r = 0; r < 8; r++)
            #pragma unroll
            for (int g = 0; g < 4; g++)
                #pragma unroll
                for (int q = 0; q < 4; q++) acc[r][g][q] = 0.f;
        gemm_k128(acc, g_T_ihd, h0s, wbuf, tid, r0, cg4);
        gemm_k128(acc, g_T_hhd, h1s, wbuf, tid, r0, cg4);
        cell_update(acc, bd, h1s, c1s, r0, cg4);
        __syncthreads();

        // layernorm + heads; warp rg handles rows r0..r0+7
        {
            int lane = cg;
            float4 g4v = *(const float4*)&ln_g[lane * 4];
            float4 b4v = *(const float4*)&ln_b[lane * 4];
            float4 wm0 = *(const float4*)&Wm[0 * HID + lane * 4];
            float4 wm1 = *(const float4*)&Wm[1 * HID + lane * 4];
            float4 wm2 = *(const float4*)&Wm[2 * HID + lane * 4];
            float4 ws0 = *(const float4*)&Ws[0 * HID + lane * 4];
            float4 ws1 = *(const float4*)&Ws[1 * HID + lane * 4];
            float4 ws2 = *(const float4*)&Ws[2 * HID + lane * 4];
            float bm0 = bm[0], bm1 = bm[1], bm2 = bm[2];
            float bs0 = bs[0], bs1 = bs[1], bs2 = bs[2];
            #pragma unroll 1
            for (int r = 0; r < 8; r++) {
                int row = r0 + r;
                float4 v = *(const float4*)&h1s[row * HID + lane * 4];
                float sum = wred(v.x + v.y + v.z + v.w);
                float mu = sum * (1.f / 128.f);
                float4 dv = make_float4(v.x - mu, v.y - mu, v.z - mu, v.w - mu);
                float ss = wred(dv.x * dv.x + dv.y * dv.y + dv.z * dv.z + dv.w * dv.w);
                float rs = rsqrtf(ss * (1.f / 128.f) + 1e-5f);
                float4 f;
                f.x = dv.x * rs * g4v.x + b4v.x;
                f.y = dv.y * rs * g4v.y + b4v.y;
                f.z = dv.z * rs * g4v.z + b4v.z;
                f.w = dv.w * rs * g4v.w + b4v.w;
                float m0 = wred(f.x * wm0.x + f.y * wm0.y + f.z * wm0.z + f.w * wm0.w);
                float m1 = wred(f.x * wm1.x + f.y * wm1.y + f.z * wm1.z + f.w * wm1.w);
                float m2 = wred(f.x * wm2.x + f.y * wm2.y + f.z * wm2.z + f.w * wm2.w);
                float s0 = wred(f.x * ws0.x + f.y * ws0.y + f.z * ws0.z + f.w * ws0.w);
                float s1 = wred(f.x * ws1.x + f.y * ws1.y + f.z * ws1.z + f.w * ws1.w);
                float s2 = wred(f.x * ws2.x + f.y * ws2.y + f.z * ws2.z + f.w * ws2.w);
                if (lane == 0) {
                    m0 += bm0; m1 += bm1; m2 += bm2;
                    float l0 = fminf(fmaxf(s0 + bs0, -6.f), 3.f);
                    float l1 = fminf(fmaxf(s1 + bs1, -6.f), 3.f);
                    float l2 = fminf(fmaxf(s2 + bs2, -6.f), 3.f);
                    size_t orow = (size_t)(base + row) * (HORZ * OUTDIM) + s * OUTDIM;
                    out[orow + 0] = m0; out[orow + 1] = m1; out[orow + 2] = m2;
                    out[LOGOFF + orow + 0] = l0;
                    out[LOGOFF + orow + 1] = l1;
                    out[LOGOFF + orow + 2] = l2;
                    prevb[row * 4 + 0] = m0;
                    prevb[row * 4 + 1] = m1;
                    prevb[row * 4 + 2] = m2;
                }
            }
        }
        __syncthreads();
    }
}

// ---------------- launch ----------------
extern "C" void kernel_launch(void* const* d_in, const int* in_sizes, int n_in,
                              void* d_out, int out_size) {
    const float* x     = (const float*)d_in[0];
    const float* W_ih0 = (const float*)d_in[1];
    const float* W_hh0 = (const float*)d_in[2];
    const float* b0    = (const float*)d_in[3];
    const float* W_ih1 = (const float*)d_in[4];
    const float* W_hh1 = (const float*)d_in[5];
    const float* b1    = (const float*)d_in[6];
    const float* W_ihd = (const float*)d_in[7];
    const float* W_hhd = (const float*)d_in[8];
    const float* bd    = (const float*)d_in[9];
    const float* emb   = (const float*)d_in[10];
    const float* Wp    = (const float*)d_in[11];
    const float* bp    = (const float*)d_in[12];
    const float* Wm    = (const float*)d_in[13];
    const float* bm    = (const float*)d_in[14];
    const float* Ws    = (const float*)d_in[15];
    const float* bs    = (const float*)d_in[16];
    const float* ln_g  = (const float*)d_in[17];
    const float* ln_b  = (const float*)d_in[18];
    float* out = (float*)d_out;

    (void)in_sizes; (void)n_in; (void)out_size;

    prep_transpose<<<(5 * 65536 + INDIM * G4 + 255) / 256, 256>>>(W_ih0, W_hh0, W_ih1, W_hh1, W_ihd, W_hhd);
    prep_small<<<(HORZ * HID + 255) / 256, 256>>>(emb, Wp, bp);

    cudaFuncSetAttribute(traj_kernel, cudaFuncAttributeMaxDynamicSharedMemorySize, SMEM_BYTES);
    traj_kernel<<<BTOT / MROWS, NTHR, SMEM_BYTES>>>(x, b0, b1, bd, Wm, bm, Ws, bs, ln_g, ln_b, out);
}